// round 13
// baseline (speedup 1.0000x reference)
#include <cuda_runtime.h>
#include <math.h>
#include <stdint.h>

#define Bn  2
#define Sn  256
#define INn 80
#define Hn  128
#define G4  512
#define F2n 256
#define NCn 40
#define Wn  64
#define PHn 100
#define TP  132
#define CL  4      // scan cluster size (unit-split, k replicated)

// ---------------- scratch (device globals) ---------------------------------
__device__ float  g_wihT0[2][INn][G4];     // [dir][i][g]
__device__ float  g_wihT1[2][F2n][G4];
__device__ float  g_w1cT[F2n][128];        // [t][ph], ph>=100 zero
__device__ float  g_w1dT[F2n][128];
__device__ float  g_w1eT[F2n][128];
__device__ float  g_wc1T[F2n][80];         // [t][q]
__device__ float  g_wb1T[F2n][80];
__device__ float  g_preG[2][Bn][Sn][G4];   // gate pre-activations, row = gate*128+unit
__device__ float  g_out0[Bn][Sn][F2n];
__device__ float  g_rnn [Bn][Sn][F2n];
__device__ float  g_cum [Bn][Sn][F2n];
__device__ float  g_u[Bn][Sn][PHn];
__device__ float  g_v[Bn][Sn][PHn];
__device__ float  g_sband[Bn][Sn][Wn];

__device__ __forceinline__ float sigf(float x) {
    return __fdividef(1.0f, 1.0f + __expf(-x));
}
__device__ __forceinline__ float tanh_fast(float x) {
    x = fminf(fmaxf(x, -15.0f), 15.0f);
    float e = __expf(2.0f * x);
    return __fdividef(e - 1.0f, e + 1.0f);
}

// ---- cluster / mbarrier helpers -------------------------------------------
__device__ __forceinline__ uint32_t smem_u32(const void* p) {
    uint32_t a;
    asm("{ .reg .u64 t; cvta.to.shared.u64 t, %1; cvt.u32.u64 %0, t; }" : "=r"(a) : "l"(p));
    return a;
}
__device__ __forceinline__ uint32_t mapa32(uint32_t a, uint32_t rank) {
    uint32_t r; asm("mapa.shared::cluster.u32 %0, %1, %2;" : "=r"(r) : "r"(a), "r"(rank));
    return r;
}
__device__ __forceinline__ void st_cl_f32(uint32_t a, float v) {
    asm volatile("st.shared::cluster.f32 [%0], %1;" :: "r"(a), "f"(v) : "memory");
}
__device__ __forceinline__ void mbar_init(uint32_t a, uint32_t count) {
    asm volatile("mbarrier.init.shared.b64 [%0], %1;" :: "r"(a), "r"(count) : "memory");
}
__device__ __forceinline__ void arrive_rel_cluster(uint32_t a) {
    asm volatile("mbarrier.arrive.release.cluster.shared::cluster.b64 _, [%0];"
                 :: "r"(a) : "memory");
}
__device__ __forceinline__ void wait_parity_acq_cluster(uint32_t a, uint32_t par) {
    uint32_t done;
    asm volatile("{\n\t.reg .pred p;\n\t"
                 "mbarrier.try_wait.parity.acquire.cluster.shared::cta.b64 p, [%1], %2, 0x989680;\n\t"
                 "selp.b32 %0,1,0,p;\n\t}"
                 : "=r"(done) : "r"(a), "r"(par) : "memory");
    while (!done) {
        asm volatile("{\n\t.reg .pred p;\n\t"
                     "mbarrier.try_wait.parity.acquire.cluster.shared::cta.b64 p, [%1], %2, 0x989680;\n\t"
                     "selp.b32 %0,1,0,p;\n\t}"
                     : "=r"(done) : "r"(a), "r"(par) : "memory");
    }
}
#define CLUSTER_SYNC_() do { \
    asm volatile("barrier.cluster.arrive.aligned;" ::: "memory"); \
    asm volatile("barrier.cluster.wait.aligned;" ::: "memory"); } while (0)

// ---------------------------------------------------------------------------
// Weight prep
// ---------------------------------------------------------------------------
__global__ void prep_wih_kernel(const float* __restrict__ w0f, const float* __restrict__ w0b,
                                const float* __restrict__ w1f, const float* __restrict__ w1b)
{
    int idx = blockIdx.x * blockDim.x + threadIdx.x;
    const int N0 = 2 * INn * G4;
    const int N1 = 2 * F2n * G4;
    if (idx < N0) {
        int d = idx / (INn * G4), r = idx % (INn * G4);
        int i = r / G4, g = r % G4;
        g_wihT0[d][i][g] = (d ? w0b : w0f)[g * INn + i];
    } else if (idx < N0 + N1) {
        int r2 = idx - N0;
        int d = r2 / (F2n * G4), r = r2 % (F2n * G4);
        int i = r / G4, g = r % G4;
        g_wihT1[d][i][g] = (d ? w1b : w1f)[g * F2n + i];
    }
}

__global__ void prep_score_kernel(const float* __restrict__ w_s1,
                                  const float* __restrict__ w_c1,
                                  const float* __restrict__ w_b1)
{
    int idx = blockIdx.x * blockDim.x + threadIdx.x;
    const int NA = F2n * 128;
    const int NB = F2n * 80;
    if (idx < NA) {
        int t = idx >> 7, ph = idx & 127;
        g_w1cT[t][ph] = (ph < PHn) ? w_s1[ph * 768 + t] : 0.f;
    } else if (idx < 2 * NA) {
        int r = idx - NA; int t = r >> 7, ph = r & 127;
        g_w1dT[t][ph] = (ph < PHn) ? w_s1[ph * 768 + 256 + t] : 0.f;
    } else if (idx < 3 * NA) {
        int r = idx - 2 * NA; int t = r >> 7, ph = r & 127;
        g_w1eT[t][ph] = (ph < PHn) ? w_s1[ph * 768 + 512 + t] : 0.f;
    } else if (idx < 3 * NA + NB) {
        int r = idx - 3 * NA; int t = r / 80, q = r % 80;
        g_wc1T[t][q] = w_c1[q * F2n + t];
    } else if (idx < 3 * NA + 2 * NB) {
        int r = idx - 3 * NA - NB; int t = r / 80, q = r % 80;
        g_wb1T[t][q] = w_b1[q * F2n + t];
    }
}

// ---------------------------------------------------------------------------
// pre: gate pre-activations with 8-way s-blocking. One CTA per (s-tile, b, d),
// 512 threads = one gate-row g each, acc[8] over the 8 sequence positions.
// Weights streamed once per 8 positions; activations staged transposed in smem.
// ---------------------------------------------------------------------------
__global__ void __launch_bounds__(512) pre_kernel(
        const float* __restrict__ x, int layer,
        const float* __restrict__ bf, const float* __restrict__ bb)
{
    int s0 = blockIdx.x * 8, b = blockIdx.y, d = blockIdx.z;
    int g = threadIdx.x;                       // 512 threads; g = gate*128+unit
    int in_dim = layer ? F2n : INn;
    const float* base = layer ? &g_out0[b][s0][0] : (x + (b * Sn + s0) * INn);
    const float* wT = layer ? &g_wihT1[d][0][0] : &g_wihT0[d][0][0];

    __shared__ __align__(16) float xsT[F2n][8];   // [i][j], 8KB
    for (int e = g; e < 8 * in_dim; e += 512) {
        int j = e / in_dim, i = e - j * in_dim;
        xsT[i][j] = base[j * in_dim + i];
    }
    __syncthreads();

    float bias = (d ? bb : bf)[g];
    float acc[8];
    #pragma unroll
    for (int j = 0; j < 8; j++) acc[j] = bias;

    const float4* xsT4 = (const float4*)&xsT[0][0];
    #pragma unroll 4
    for (int i = 0; i < in_dim; i++) {
        float wv = wT[i * G4 + g];
        float4 xa = xsT4[i * 2], xb = xsT4[i * 2 + 1];
        acc[0] += wv * xa.x; acc[1] += wv * xa.y;
        acc[2] += wv * xa.z; acc[3] += wv * xa.w;
        acc[4] += wv * xb.x; acc[5] += wv * xb.y;
        acc[6] += wv * xb.z; acc[7] += wv * xb.w;
    }
    #pragma unroll
    for (int j = 0; j < 8; j++)
        g_preG[d][b][s0 + j][g] = acc[j];
}

// ---------------------------------------------------------------------------
// LSTM scan: cluster of 4 CTAs per (layer, dir, batch). CTA r owns units
// [32r,32r+32) with FULL k range, ONE batch. Weights in registers.
// 512 threads: t -> (kq = t>>7 in 0..3, row = t&127), row = gate*32 + u.
// Per step: 8 FFMA4/thread -> pall4 -> __syncthreads -> warp0 epilogue
// (32 units: reduce 4 quarters via one LDS.128 per gate, c/h update,
// 128B h-broadcast to 4 ranks, __syncwarp, lanes 0..3 release-arrive).
// ---------------------------------------------------------------------------
__global__ void __cluster_dims__(CL, 1, 1) __launch_bounds__(512, 1)
scan_kernel(int layer, const float* __restrict__ whhF, const float* __restrict__ whhB)
{
    int r = blockIdx.x;           // cluster rank (unit group)
    int d = blockIdx.y;           // direction
    int b = blockIdx.z;           // batch
    int t = threadIdx.x;          // 0..511
    int row = t & 127;            // gate*32 + u
    int kq  = t >> 7;             // k quarter (0..3)
    int gate = row >> 5, u = row & 31;

    __shared__ __align__(16) float  hbuf[2][Hn];   // [parity][k]
    __shared__ __align__(16) float4 pall4[128];    // [row] = (kq0,kq1,kq2,kq3)
    __shared__ __align__(8) unsigned long long mbar[2];

    uint32_t barL = smem_u32(&mbar[0]);
    if (t == 0) { mbar_init(barL, CL); mbar_init(barL + 8, CL); }
    if (t < Hn) { hbuf[0][t] = 0.f; hbuf[1][t] = 0.f; }

    // load this thread's 32-k weight quarter into registers (once)
    const float* whh = d ? whhB : whhF;
    const float4* wsrc = (const float4*)(whh + (gate * Hn + r * 32 + u) * Hn + kq * 32);
    float4 w[8];
    #pragma unroll
    for (int q = 0; q < 8; q++) w[q] = wsrc[q];

    __syncthreads();
    CLUSTER_SYNC_();

    float* out = layer ? &g_rnn[0][0][0] : &g_out0[0][0][0];
    const float* preB = &g_preG[d][b][0][0];          // [s][512]
    int prow = gate * Hn + r * 32 + u;
    float pm = (kq == 0) ? 1.f : 0.f;                 // only kq==0 carries pre

    // epilogue mapping (warp 0): unit = t (t<32)
    float cst = 0.f;
    uint32_t hA = smem_u32(&hbuf[0][r * 32 + (t & 31)]);
    uint32_t hD0 = mapa32(hA, 0), hD1 = mapa32(hA, 1),
             hD2 = mapa32(hA, 2), hD3 = mapa32(hA, 3);
    uint32_t barArr = (t < CL) ? mapa32(barL, (uint32_t)t) : 0u;
    const uint32_t HST = (uint32_t)(Hn * sizeof(float));   // parity stride

    unsigned wp0 = 0, wp1 = 0;

    int sf = d ? (Sn - 1) : 0;
    float pr = preB[sf * G4 + prow] * pm;

    for (int n = 0; n < Sn; n++) {
        int p = n & 1;
        if (n) {
            if (p) { wait_parity_acq_cluster(barL + 8, wp1); wp1 ^= 1; }
            else   { wait_parity_acq_cluster(barL,     wp0); wp0 ^= 1; }
        }
        int s = d ? (Sn - 1 - n) : n;

        const float4* h4 = (const float4*)&hbuf[p][kq * 32];
        float a0 = pr, a1 = 0.f;
        #pragma unroll
        for (int q = 0; q < 8; q += 2) {
            float4 w0 = w[q], w1 = w[q + 1];
            float4 v0 = h4[q], v1 = h4[q + 1];
            a0 += w0.x * v0.x + w0.y * v0.y + w0.z * v0.z + w0.w * v0.w;
            a1 += w1.x * v1.x + w1.y * v1.y + w1.z * v1.z + w1.w * v1.w;
        }
        ((float*)&pall4[row])[kq] = a0 + a1;

        // prefetch next step's pre (latency hides under epilogue/wait)
        if (n + 1 < Sn) {
            int sn = d ? (Sn - 2 - n) : (n + 1);
            pr = preB[sn * G4 + prow] * pm;
        }
        __syncthreads();

        if (t < 32) {
            float4 q0 = pall4[t], q1 = pall4[32 + t];
            float4 q2 = pall4[64 + t], q3 = pall4[96 + t];
            float gi = q0.x + q0.y + q0.z + q0.w;
            float gf = q1.x + q1.y + q1.z + q1.w;
            float gg = q2.x + q2.y + q2.z + q2.w;
            float go = q3.x + q3.y + q3.z + q3.w;
            cst = sigf(gf) * cst + sigf(gi) * tanh_fast(gg);
            float h = sigf(go) * tanh_fast(cst);
            out[(b * Sn + s) * F2n + d * Hn + (r * 32 + t)] = h;
            uint32_t off = (uint32_t)(p ^ 1) * HST;
            st_cl_f32(hD0 + off, h);
            st_cl_f32(hD1 + off, h);
            st_cl_f32(hD2 + off, h);
            st_cl_f32(hD3 + off, h);
            __syncwarp();
            if (t < CL) arrive_rel_cluster(barArr + (uint32_t)(p ^ 1) * 8u);
        }
    }
    CLUSTER_SYNC_();
}

// ---------------------------------------------------------------------------
__global__ void cum_kernel()
{
    int b = blockIdx.x, t = threadIdx.x;       // 256 threads
    float acc = 0.f;
    for (int s = 0; s < Sn; s++) { acc += g_rnn[b][s][t]; g_cum[b][s][t] = acc; }
}

// ---------------------------------------------------------------------------
// Per-position u/v projections + cls/bin heads
// ---------------------------------------------------------------------------
__global__ void feat_kernel(const float* __restrict__ a_s0p,
                            const float* __restrict__ a_c0p, const float* __restrict__ b_c1,
                            const float* __restrict__ a_c1p, const float* __restrict__ w_c2,
                            const float* __restrict__ b_c2,
                            const float* __restrict__ a_b0p, const float* __restrict__ b_b1,
                            const float* __restrict__ a_b1p, const float* __restrict__ w_b2,
                            const float* __restrict__ b_b2,
                            float* __restrict__ out)
{
    int s = blockIdx.x, b = blockIdx.y, tid = threadIdx.x;   // 128 threads
    __shared__ float prs[F2n], prc[F2n], prb[F2n];
    __shared__ float hc[80], hb[80];
    float as0 = *a_s0p, ac0 = *a_c0p, ac1 = *a_c1p, ab0 = *a_b0p, ab1 = *a_b1p;

    for (int i = tid; i < F2n; i += 128) {
        float xv = g_rnn[b][s][i];
        prs[i] = xv >= 0.f ? xv : as0 * xv;
        prc[i] = xv >= 0.f ? xv : ac0 * xv;
        prb[i] = xv >= 0.f ? xv : ab0 * xv;
    }
    __syncthreads();

    if (tid < PHn) {
        float au = 0.f, av = 0.f;
        #pragma unroll 8
        for (int i = 0; i < F2n; i++) {
            float p = prs[i];
            au += g_w1dT[i][tid] * p;
            av += g_w1eT[i][tid] * p;
        }
        g_u[b][s][tid] = au;
        g_v[b][s][tid] = av;
    }
    if (tid < 80) {
        float a1 = b_c1[tid], a2 = b_b1[tid];
        #pragma unroll 8
        for (int i = 0; i < F2n; i++) {
            a1 += g_wc1T[i][tid] * prc[i];
            a2 += g_wb1T[i][tid] * prb[i];
        }
        hc[tid] = a1 >= 0.f ? a1 : ac1 * a1;
        hb[tid] = a2 >= 0.f ? a2 : ab1 * a2;
    }
    __syncthreads();
    if (tid < NCn) {
        float acc = b_c2[tid];
        const float* w = w_c2 + tid * 80;
        #pragma unroll 8
        for (int i = 0; i < 80; i++) acc += w[i] * hc[i];
        out[(b * Sn + s) * NCn + tid] = acc;
    }
    if (tid < 2) {
        float acc = b_b2[tid];
        const float* w = w_b2 + tid * 80;
        for (int i = 0; i < 80; i++) acc += w[i] * hb[i];
        out[Bn * Sn * NCn + (b * Sn + s) * 2 + tid] = acc;
    }
}

// ---------------------------------------------------------------------------
// Banded scores, one CTA per (b, i)
// ---------------------------------------------------------------------------
__global__ void __launch_bounds__(128) sband_kernel(
        const float* __restrict__ a_s0p, const float* __restrict__ b_s1,
        const float* __restrict__ a_s1p, const float* __restrict__ w_s2,
        const float* __restrict__ b_s2)
{
    int i = blockIdx.x + 1, b = blockIdx.y, tid = threadIdx.x;  // 128 threads
    int start = i - Wn; if (start < 0) start = 0;

    __shared__ __align__(16) float pd[Wn * TP];
    float acc[Wn];
    #pragma unroll
    for (int j = 0; j < Wn; j++) acc[j] = 0.f;

    float as0 = *a_s0p;

    for (int pass = 0; pass < 2; pass++) {
        int tb = pass * 128;
        float cI = g_cum[b][i][tb + tid];
        for (int j = 0; j < Wn; j++) {
            float dc = cI - g_cum[b][start + j][tb + tid];
            pd[j * TP + tid] = dc >= 0.f ? dc : as0 * dc;
        }
        __syncthreads();

        for (int t0 = 0; t0 < 128; t0 += 4) {
            float w0 = g_w1cT[tb + t0][tid];
            float w1 = g_w1cT[tb + t0 + 1][tid];
            float w2 = g_w1cT[tb + t0 + 2][tid];
            float w3 = g_w1cT[tb + t0 + 3][tid];
            #pragma unroll
            for (int j = 0; j < Wn; j++) {
                float4 p = *(const float4*)&pd[j * TP + t0];
                acc[j] += w0 * p.x + w1 * p.y + w2 * p.z + w3 * p.w;
            }
        }
        __syncthreads();
    }

    float* red = pd;
    float wsc  = tid < PHn ? w_s2[tid] : 0.f;
    float bs1v = tid < PHn ? b_s1[tid] : 0.f;
    float vi   = tid < PHn ? g_v[b][i][tid] : 0.f;
    float as1  = *a_s1p;

    for (int j = 0; j < Wn; j++) {
        if (tid < PHn) {
            float uj = g_u[b][start + j][tid];
            float hs = acc[j] + bs1v + uj + vi;
            float pr = hs >= 0.f ? hs : as1 * hs;
            red[j * 101 + tid] = pr * wsc;
        }
    }
    __syncthreads();
    if (tid < Wn) {
        float s = *b_s2;
        #pragma unroll 4
        for (int p = 0; p < PHn; p++) s += red[tid * 101 + p];
        g_sband[b][i][tid] = s;
    }
}

// ---------------------------------------------------------------------------
// DP + backtrack: one warp per batch, no __syncthreads in the hot loop.
// ---------------------------------------------------------------------------
__global__ void dp_kernel(const int* __restrict__ lengths, float* __restrict__ out)
{
    int tid = threadIdx.x;                     // 64 threads = 2 warps
    int b = tid >> 5, lane = tid & 31;
    __shared__ float best[Bn][Sn];
    __shared__ float esc[Bn][Sn];
    __shared__ int   bpS[Bn][Sn];

    for (int idx = tid; idx < Bn * Sn; idx += 64) ((float*)best)[idx] = 0.f;
    __syncthreads();

    float sa  = g_sband[b][1][lane];
    float sb2 = g_sband[b][1][lane + 32];
    for (int i = 1; i < Sn; i++) {
        float s0 = sa, s1 = sb2;
        if (i + 1 < Sn) { sa = g_sband[b][i + 1][lane]; sb2 = g_sband[b][i + 1][lane + 32]; }
        int start = i - Wn; if (start < 0) start = 0;
        int j0 = start + lane, j1 = start + lane + 32;
        unsigned long long key = 0ull;
        float v0 = 0.f, v1 = 0.f;
        if (j0 < i) {
            v0 = best[b][j0] + s0;
            unsigned u = __float_as_uint(v0);
            u = (u & 0x80000000u) ? ~u : (u | 0x80000000u);
            key = ((unsigned long long)u << 32) | (unsigned)(0xFFFFFFFFu - (unsigned)j0);
        }
        if (j1 < i) {
            v1 = best[b][j1] + s1;
            unsigned u = __float_as_uint(v1);
            u = (u & 0x80000000u) ? ~u : (u | 0x80000000u);
            unsigned long long k1 = ((unsigned long long)u << 32) | (unsigned)(0xFFFFFFFFu - (unsigned)j1);
            if (k1 > key) key = k1;
        }
        #pragma unroll
        for (int off = 16; off; off >>= 1) {
            unsigned long long ok = __shfl_down_sync(0xffffffffu, key, off);
            if (ok > key) key = ok;
        }
        key = __shfl_sync(0xffffffffu, key, 0);
        int jstar = (int)(0xFFFFFFFFu - (unsigned)(key & 0xFFFFFFFFull));
        if (j0 == jstar && j0 < i) { best[b][i] = v0; bpS[b][i] = jstar; esc[b][i] = s0; }
        if (j1 == jstar && j1 < i) { best[b][i] = v1; bpS[b][i] = jstar; esc[b][i] = s1; }
        __syncwarp();
    }
    __syncthreads();

    // ---- backtrack ----
    float* bm = out + Bn * Sn * NCn + Bn * Sn * 2;
    for (int idx = tid; idx < Bn * Sn; idx += 64) bm[idx] = 0.f;
    if (tid < Bn) { bpS[tid][0] = 0; esc[tid][0] = 0.f; }
    __syncthreads();
    if (lane == 0) {
        int cur = lengths[b] - 1;
        float acc = 0.f;
        for (int st2 = 0; st2 < Sn; st2++) {
            bm[b * Sn + cur] = 1.0f;
            int prev = bpS[b][cur];
            if (cur > 0) { acc += esc[b][cur]; cur = prev; }
        }
        out[Bn * Sn * NCn + Bn * Sn * 2 + Bn * Sn + b] = acc;
    }
}

// ---------------------------------------------------------------------------
extern "C" void kernel_launch(void* const* d_in, const int* in_sizes, int n_in,
                              void* d_out, int out_size)
{
    const float* x        = (const float*)d_in[0];
    const int*   lengths  = (const int*)  d_in[1];
    const float* w_ih_l0f = (const float*)d_in[2];
    const float* w_hh_l0f = (const float*)d_in[3];
    const float* b_l0f    = (const float*)d_in[4];
    const float* w_ih_l0b = (const float*)d_in[5];
    const float* w_hh_l0b = (const float*)d_in[6];
    const float* b_l0b    = (const float*)d_in[7];
    const float* w_ih_l1f = (const float*)d_in[8];
    const float* w_hh_l1f = (const float*)d_in[9];
    const float* b_l1f    = (const float*)d_in[10];
    const float* w_ih_l1b = (const float*)d_in[11];
    const float* w_hh_l1b = (const float*)d_in[12];
    const float* b_l1b    = (const float*)d_in[13];
    const float* a_s0     = (const float*)d_in[14];
    const float* w_s1     = (const float*)d_in[15];
    const float* b_s1     = (const float*)d_in[16];
    const float* a_s1     = (const float*)d_in[17];
    const float* w_s2     = (const float*)d_in[18];
    const float* b_s2     = (const float*)d_in[19];
    const float* a_c0     = (const float*)d_in[20];
    const float* w_c1     = (const float*)d_in[21];
    const float* b_c1     = (const float*)d_in[22];
    const float* a_c1     = (const float*)d_in[23];
    const float* w_c2     = (const float*)d_in[24];
    const float* b_c2     = (const float*)d_in[25];
    const float* a_b0     = (const float*)d_in[26];
    const float* w_b1     = (const float*)d_in[27];
    const float* b_b1     = (const float*)d_in[28];
    const float* a_b1     = (const float*)d_in[29];
    const float* w_b2     = (const float*)d_in[30];
    const float* b_b2     = (const float*)d_in[31];
    float* out = (float*)d_out;

    // launches ordered so that ncu (-s 5 -c 1) lands on a scan_kernel
    prep_wih_kernel<<<(2 * INn * G4 + 2 * F2n * G4 + 255) / 256, 256>>>(
        w_ih_l0f, w_ih_l0b, w_ih_l1f, w_ih_l1b);                                       // 1
    pre_kernel<<<dim3(Sn / 8, Bn, 2), 512>>>(x, 0, b_l0f, b_l0b);                      // 2
    scan_kernel<<<dim3(CL, 2, Bn), 512>>>(0, w_hh_l0f, w_hh_l0b);                      // 3
    pre_kernel<<<dim3(Sn / 8, Bn, 2), 512>>>(x, 1, b_l1f, b_l1b);                      // 4
    prep_score_kernel<<<(3 * F2n * 128 + 2 * F2n * 80 + 255) / 256, 256>>>(w_s1, w_c1, w_b1); // 5
    scan_kernel<<<dim3(CL, 2, Bn), 512>>>(1, w_hh_l1f, w_hh_l1b);                      // 6 <- profiled
    cum_kernel<<<Bn, F2n>>>();                                                         // 7
    feat_kernel<<<dim3(Sn, Bn), 128>>>(a_s0, a_c0, b_c1, a_c1, w_c2, b_c2,
                                       a_b0, b_b1, a_b1, w_b2, b_b2, out);             // 8
    sband_kernel<<<dim3(Sn - 1, Bn), 128>>>(a_s0, b_s1, a_s1, w_s2, b_s2);             // 9
    dp_kernel<<<1, 64>>>(lengths, out);                                                // 10
}

// round 15
// speedup vs baseline: 1.0956x; 1.0956x over previous
#include <cuda_runtime.h>
#include <math.h>
#include <stdint.h>

#define Bn  2
#define Sn  256
#define INn 80
#define Hn  128
#define G4  512
#define F2n 256
#define NCn 40
#define Wn  64
#define PHn 100
#define TP  132
#define CL  4      // scan cluster size (unit-split, k replicated)

// ---------------- scratch (device globals) ---------------------------------
__device__ float  g_wihT0[2][INn][G4];     // [dir][i][g]
__device__ float  g_wihT1[2][F2n][G4];
__device__ float  g_w1cT[F2n][128];        // [t][ph], ph>=100 zero
__device__ float  g_w1dT[F2n][128];
__device__ float  g_w1eT[F2n][128];
__device__ float  g_wc1T[F2n][80];         // [t][q]
__device__ float  g_wb1T[F2n][80];
__device__ float  g_preG[2][Bn][Sn][G4];   // gate pre-activations, row = gate*128+unit
__device__ float  g_out0[Bn][Sn][F2n];
__device__ float  g_rnn [Bn][Sn][F2n];
__device__ float  g_cum [Bn][Sn][F2n];
__device__ float  g_u[Bn][Sn][PHn];
__device__ float  g_v[Bn][Sn][PHn];
__device__ float  g_sband[Bn][Sn][Wn];

__device__ __forceinline__ float sigf(float x) {
    return __fdividef(1.0f, 1.0f + __expf(-x));
}
__device__ __forceinline__ float tanh_fast(float x) {
    x = fminf(fmaxf(x, -15.0f), 15.0f);
    float e = __expf(2.0f * x);
    return __fdividef(e - 1.0f, e + 1.0f);
}

// ---- cluster / mbarrier helpers -------------------------------------------
__device__ __forceinline__ uint32_t smem_u32(const void* p) {
    uint32_t a;
    asm("{ .reg .u64 t; cvta.to.shared.u64 t, %1; cvt.u32.u64 %0, t; }" : "=r"(a) : "l"(p));
    return a;
}
__device__ __forceinline__ uint32_t mapa32(uint32_t a, uint32_t rank) {
    uint32_t r; asm("mapa.shared::cluster.u32 %0, %1, %2;" : "=r"(r) : "r"(a), "r"(rank));
    return r;
}
__device__ __forceinline__ void st_cl_f32(uint32_t a, float v) {
    asm volatile("st.shared::cluster.f32 [%0], %1;" :: "r"(a), "f"(v) : "memory");
}
__device__ __forceinline__ void mbar_init(uint32_t a, uint32_t count) {
    asm volatile("mbarrier.init.shared.b64 [%0], %1;" :: "r"(a), "r"(count) : "memory");
}
__device__ __forceinline__ void arrive_rel_cluster(uint32_t a) {
    asm volatile("mbarrier.arrive.release.cluster.shared::cluster.b64 _, [%0];"
                 :: "r"(a) : "memory");
}
__device__ __forceinline__ void wait_parity_acq_cluster(uint32_t a, uint32_t par) {
    uint32_t done;
    asm volatile("{\n\t.reg .pred p;\n\t"
                 "mbarrier.try_wait.parity.acquire.cluster.shared::cta.b64 p, [%1], %2, 0x989680;\n\t"
                 "selp.b32 %0,1,0,p;\n\t}"
                 : "=r"(done) : "r"(a), "r"(par) : "memory");
    while (!done) {
        asm volatile("{\n\t.reg .pred p;\n\t"
                     "mbarrier.try_wait.parity.acquire.cluster.shared::cta.b64 p, [%1], %2, 0x989680;\n\t"
                     "selp.b32 %0,1,0,p;\n\t}"
                     : "=r"(done) : "r"(a), "r"(par) : "memory");
    }
}
#define CLUSTER_SYNC_() do { \
    asm volatile("barrier.cluster.arrive.aligned;" ::: "memory"); \
    asm volatile("barrier.cluster.wait.aligned;" ::: "memory"); } while (0)

// ---------------------------------------------------------------------------
// Weight prep
// ---------------------------------------------------------------------------
__global__ void prep_wih_kernel(const float* __restrict__ w0f, const float* __restrict__ w0b,
                                const float* __restrict__ w1f, const float* __restrict__ w1b)
{
    int idx = blockIdx.x * blockDim.x + threadIdx.x;
    const int N0 = 2 * INn * G4;
    const int N1 = 2 * F2n * G4;
    if (idx < N0) {
        int d = idx / (INn * G4), r = idx % (INn * G4);
        int i = r / G4, g = r % G4;
        g_wihT0[d][i][g] = (d ? w0b : w0f)[g * INn + i];
    } else if (idx < N0 + N1) {
        int r2 = idx - N0;
        int d = r2 / (F2n * G4), r = r2 % (F2n * G4);
        int i = r / G4, g = r % G4;
        g_wihT1[d][i][g] = (d ? w1b : w1f)[g * F2n + i];
    }
}

__global__ void prep_score_kernel(const float* __restrict__ w_s1,
                                  const float* __restrict__ w_c1,
                                  const float* __restrict__ w_b1)
{
    int idx = blockIdx.x * blockDim.x + threadIdx.x;
    const int NA = F2n * 128;
    const int NB = F2n * 80;
    if (idx < NA) {
        int t = idx >> 7, ph = idx & 127;
        g_w1cT[t][ph] = (ph < PHn) ? w_s1[ph * 768 + t] : 0.f;
    } else if (idx < 2 * NA) {
        int r = idx - NA; int t = r >> 7, ph = r & 127;
        g_w1dT[t][ph] = (ph < PHn) ? w_s1[ph * 768 + 256 + t] : 0.f;
    } else if (idx < 3 * NA) {
        int r = idx - 2 * NA; int t = r >> 7, ph = r & 127;
        g_w1eT[t][ph] = (ph < PHn) ? w_s1[ph * 768 + 512 + t] : 0.f;
    } else if (idx < 3 * NA + NB) {
        int r = idx - 3 * NA; int t = r / 80, q = r % 80;
        g_wc1T[t][q] = w_c1[q * F2n + t];
    } else if (idx < 3 * NA + 2 * NB) {
        int r = idx - 3 * NA - NB; int t = r / 80, q = r % 80;
        g_wb1T[t][q] = w_b1[q * F2n + t];
    }
}

// ---------------------------------------------------------------------------
// pre: gate pre-activations, scalar layout row = gate*128+unit
// ---------------------------------------------------------------------------
__global__ void pre_kernel(const float* __restrict__ x, int layer,
                           const float* __restrict__ bf, const float* __restrict__ bb)
{
    int s = blockIdx.x, b = blockIdx.y, d = blockIdx.z;
    int g = threadIdx.x;                       // 512 threads; g = gate*128+unit
    int in_dim = layer ? F2n : INn;
    const float* row = layer ? &g_out0[b][s][0] : (x + (b * Sn + s) * INn);
    const float* wT = layer ? &g_wihT1[d][0][0] : &g_wihT0[d][0][0];

    __shared__ float xs[F2n];
    for (int i = g; i < in_dim; i += blockDim.x) xs[i] = row[i];
    __syncthreads();

    float acc = (d ? bb : bf)[g];
    #pragma unroll 8
    for (int i = 0; i < in_dim; i++) acc += wT[i * G4 + g] * xs[i];

    g_preG[d][b][s][g] = acc;
}

// ---------------------------------------------------------------------------
// LSTM scan: cluster of 4 CTAs per (layer, dir, batch). CTA r owns units
// [32r,32r+32) with FULL k range, ONE batch. Weights in registers.
// 256 threads: t -> (kh = t>>7, row = t&127), row = gate*32 + u.
// Per step: 16 FFMA4/thread -> pall -> __syncthreads -> warp0 epilogue
// (32 units: reduce 2 halves, c/h update, 128B h-broadcast to 4 ranks,
// __syncwarp, lanes 0..3 release-arrive). One syncthreads per step.
// ---------------------------------------------------------------------------
__global__ void __cluster_dims__(CL, 1, 1) __launch_bounds__(256, 1)
scan_kernel(int layer, const float* __restrict__ whhF, const float* __restrict__ whhB)
{
    int r = blockIdx.x;           // cluster rank (unit group)
    int d = blockIdx.y;           // direction
    int b = blockIdx.z;           // batch
    int t = threadIdx.x;          // 0..255
    int row = t & 127;            // gate*32 + u
    int kh  = t >> 7;             // k half
    int gate = row >> 5, u = row & 31;

    __shared__ __align__(16) float hbuf[2][Hn];   // [parity][k]
    __shared__ float pall[2][128];                // [kh][row]
    __shared__ __align__(8) unsigned long long mbar[2];

    uint32_t barL = smem_u32(&mbar[0]);
    if (t == 0) { mbar_init(barL, CL); mbar_init(barL + 8, CL); }
    if (t < Hn) { hbuf[0][t] = 0.f; hbuf[1][t] = 0.f; }

    // load this thread's weight row half into registers (once)
    const float* whh = d ? whhB : whhF;
    const float4* wsrc = (const float4*)(whh + (gate * Hn + r * 32 + u) * Hn + kh * 64);
    float4 w[16];
    #pragma unroll
    for (int q = 0; q < 16; q++) w[q] = wsrc[q];

    __syncthreads();
    CLUSTER_SYNC_();

    float* out = layer ? &g_rnn[0][0][0] : &g_out0[0][0][0];
    const float* preB = &g_preG[d][b][0][0];          // [s][512]
    int prow = gate * Hn + r * 32 + u;

    // epilogue mapping (warp 0): unit = t (t<32)
    float cst = 0.f;
    uint32_t hA = smem_u32(&hbuf[0][r * 32 + (t & 31)]);
    uint32_t hD0 = mapa32(hA, 0), hD1 = mapa32(hA, 1),
             hD2 = mapa32(hA, 2), hD3 = mapa32(hA, 3);
    uint32_t barArr = (t < CL) ? mapa32(barL, (uint32_t)t) : 0u;
    const uint32_t HST = (uint32_t)(Hn * sizeof(float));   // parity stride

    unsigned wp0 = 0, wp1 = 0;

    int sf = d ? (Sn - 1) : 0;
    float pr = (kh == 0) ? preB[sf * G4 + prow] : 0.f;

    for (int n = 0; n < Sn; n++) {
        int p = n & 1;
        if (n) {
            if (p) { wait_parity_acq_cluster(barL + 8, wp1); wp1 ^= 1; }
            else   { wait_parity_acq_cluster(barL,     wp0); wp0 ^= 1; }
        }
        int s = d ? (Sn - 1 - n) : n;

        const float4* h4 = (const float4*)&hbuf[p][kh * 64];
        float a = pr;
        #pragma unroll
        for (int q = 0; q < 16; q++) {
            float4 wq = w[q];
            float4 v = h4[q];
            a += wq.x * v.x + wq.y * v.y + wq.z * v.z + wq.w * v.w;
        }
        pall[kh][row] = a;

        // prefetch next step's pre (latency hides under epilogue/wait)
        if (kh == 0 && n + 1 < Sn) {
            int sn = d ? (Sn - 2 - n) : (n + 1);
            pr = preB[sn * G4 + prow];
        }
        __syncthreads();

        if (t < 32) {
            float gi = pall[0][t]      + pall[1][t];
            float gf = pall[0][32 + t] + pall[1][32 + t];
            float gg = pall[0][64 + t] + pall[1][64 + t];
            float go = pall[0][96 + t] + pall[1][96 + t];
            cst = sigf(gf) * cst + sigf(gi) * tanh_fast(gg);
            float h = sigf(go) * tanh_fast(cst);
            uint32_t off = (uint32_t)(p ^ 1) * HST;
            st_cl_f32(hD0 + off, h);
            st_cl_f32(hD1 + off, h);
            st_cl_f32(hD2 + off, h);
            st_cl_f32(hD3 + off, h);
            out[(b * Sn + s) * F2n + d * Hn + (r * 32 + t)] = h;
            __syncwarp();
            if (t < CL) arrive_rel_cluster(barArr + (uint32_t)(p ^ 1) * 8u);
        }
    }
    CLUSTER_SYNC_();
}

// ---------------------------------------------------------------------------
__global__ void cum_kernel()
{
    int b = blockIdx.x, t = threadIdx.x;       // 256 threads
    float acc = 0.f;
    for (int s = 0; s < Sn; s++) { acc += g_rnn[b][s][t]; g_cum[b][s][t] = acc; }
}

// ---------------------------------------------------------------------------
// Per-position u/v projections + cls/bin heads
// ---------------------------------------------------------------------------
__global__ void feat_kernel(const float* __restrict__ a_s0p,
                            const float* __restrict__ a_c0p, const float* __restrict__ b_c1,
                            const float* __restrict__ a_c1p, const float* __restrict__ w_c2,
                            const float* __restrict__ b_c2,
                            const float* __restrict__ a_b0p, const float* __restrict__ b_b1,
                            const float* __restrict__ a_b1p, const float* __restrict__ w_b2,
                            const float* __restrict__ b_b2,
                            float* __restrict__ out)
{
    int s = blockIdx.x, b = blockIdx.y, tid = threadIdx.x;   // 128 threads
    __shared__ float prs[F2n], prc[F2n], prb[F2n];
    __shared__ float hc[80], hb[80];
    float as0 = *a_s0p, ac0 = *a_c0p, ac1 = *a_c1p, ab0 = *a_b0p, ab1 = *a_b1p;

    for (int i = tid; i < F2n; i += 128) {
        float xv = g_rnn[b][s][i];
        prs[i] = xv >= 0.f ? xv : as0 * xv;
        prc[i] = xv >= 0.f ? xv : ac0 * xv;
        prb[i] = xv >= 0.f ? xv : ab0 * xv;
    }
    __syncthreads();

    if (tid < PHn) {
        float au = 0.f, av = 0.f;
        #pragma unroll 8
        for (int i = 0; i < F2n; i++) {
            float p = prs[i];
            au += g_w1dT[i][tid] * p;
            av += g_w1eT[i][tid] * p;
        }
        g_u[b][s][tid] = au;
        g_v[b][s][tid] = av;
    }
    if (tid < 80) {
        float a1 = b_c1[tid], a2 = b_b1[tid];
        #pragma unroll 8
        for (int i = 0; i < F2n; i++) {
            a1 += g_wc1T[i][tid] * prc[i];
            a2 += g_wb1T[i][tid] * prb[i];
        }
        hc[tid] = a1 >= 0.f ? a1 : ac1 * a1;
        hb[tid] = a2 >= 0.f ? a2 : ab1 * a2;
    }
    __syncthreads();
    if (tid < NCn) {
        float acc = b_c2[tid];
        const float* w = w_c2 + tid * 80;
        #pragma unroll 8
        for (int i = 0; i < 80; i++) acc += w[i] * hc[i];
        out[(b * Sn + s) * NCn + tid] = acc;
    }
    if (tid < 2) {
        float acc = b_b2[tid];
        const float* w = w_b2 + tid * 80;
        for (int i = 0; i < 80; i++) acc += w[i] * hb[i];
        out[Bn * Sn * NCn + (b * Sn + s) * 2 + tid] = acc;
    }
}

// ---------------------------------------------------------------------------
// Banded scores, one CTA per (b, i)
// ---------------------------------------------------------------------------
__global__ void __launch_bounds__(128) sband_kernel(
        const float* __restrict__ a_s0p, const float* __restrict__ b_s1,
        const float* __restrict__ a_s1p, const float* __restrict__ w_s2,
        const float* __restrict__ b_s2)
{
    int i = blockIdx.x + 1, b = blockIdx.y, tid = threadIdx.x;  // 128 threads
    int start = i - Wn; if (start < 0) start = 0;

    __shared__ __align__(16) float pd[Wn * TP];
    float acc[Wn];
    #pragma unroll
    for (int j = 0; j < Wn; j++) acc[j] = 0.f;

    float as0 = *a_s0p;

    for (int pass = 0; pass < 2; pass++) {
        int tb = pass * 128;
        float cI = g_cum[b][i][tb + tid];
        for (int j = 0; j < Wn; j++) {
            float dc = cI - g_cum[b][start + j][tb + tid];
            pd[j * TP + tid] = dc >= 0.f ? dc : as0 * dc;
        }
        __syncthreads();

        for (int t0 = 0; t0 < 128; t0 += 4) {
            float w0 = g_w1cT[tb + t0][tid];
            float w1 = g_w1cT[tb + t0 + 1][tid];
            float w2 = g_w1cT[tb + t0 + 2][tid];
            float w3 = g_w1cT[tb + t0 + 3][tid];
            #pragma unroll
            for (int j = 0; j < Wn; j++) {
                float4 p = *(const float4*)&pd[j * TP + t0];
                acc[j] += w0 * p.x + w1 * p.y + w2 * p.z + w3 * p.w;
            }
        }
        __syncthreads();
    }

    float* red = pd;
    float wsc  = tid < PHn ? w_s2[tid] : 0.f;
    float bs1v = tid < PHn ? b_s1[tid] : 0.f;
    float vi   = tid < PHn ? g_v[b][i][tid] : 0.f;
    float as1  = *a_s1p;

    for (int j = 0; j < Wn; j++) {
        if (tid < PHn) {
            float uj = g_u[b][start + j][tid];
            float hs = acc[j] + bs1v + uj + vi;
            float pr = hs >= 0.f ? hs : as1 * hs;
            red[j * 101 + tid] = pr * wsc;
        }
    }
    __syncthreads();
    if (tid < Wn) {
        float s = *b_s2;
        #pragma unroll 4
        for (int p = 0; p < PHn; p++) s += red[tid * 101 + p];
        g_sband[b][i][tid] = s;
    }
}

// ---------------------------------------------------------------------------
// DP + backtrack: one warp per batch, no __syncthreads in the hot loop.
// ---------------------------------------------------------------------------
__global__ void dp_kernel(const int* __restrict__ lengths, float* __restrict__ out)
{
    int tid = threadIdx.x;                     // 64 threads = 2 warps
    int b = tid >> 5, lane = tid & 31;
    __shared__ float best[Bn][Sn];
    __shared__ float esc[Bn][Sn];
    __shared__ int   bpS[Bn][Sn];

    for (int idx = tid; idx < Bn * Sn; idx += 64) ((float*)best)[idx] = 0.f;
    __syncthreads();

    float sa  = g_sband[b][1][lane];
    float sb2 = g_sband[b][1][lane + 32];
    for (int i = 1; i < Sn; i++) {
        float s0 = sa, s1 = sb2;
        if (i + 1 < Sn) { sa = g_sband[b][i + 1][lane]; sb2 = g_sband[b][i + 1][lane + 32]; }
        int start = i - Wn; if (start < 0) start = 0;
        int j0 = start + lane, j1 = start + lane + 32;
        unsigned long long key = 0ull;
        float v0 = 0.f, v1 = 0.f;
        if (j0 < i) {
            v0 = best[b][j0] + s0;
            unsigned u = __float_as_uint(v0);
            u = (u & 0x80000000u) ? ~u : (u | 0x80000000u);
            key = ((unsigned long long)u << 32) | (unsigned)(0xFFFFFFFFu - (unsigned)j0);
        }
        if (j1 < i) {
            v1 = best[b][j1] + s1;
            unsigned u = __float_as_uint(v1);
            u = (u & 0x80000000u) ? ~u : (u | 0x80000000u);
            unsigned long long k1 = ((unsigned long long)u << 32) | (unsigned)(0xFFFFFFFFu - (unsigned)j1);
            if (k1 > key) key = k1;
        }
        #pragma unroll
        for (int off = 16; off; off >>= 1) {
            unsigned long long ok = __shfl_down_sync(0xffffffffu, key, off);
            if (ok > key) key = ok;
        }
        key = __shfl_sync(0xffffffffu, key, 0);
        int jstar = (int)(0xFFFFFFFFu - (unsigned)(key & 0xFFFFFFFFull));
        if (j0 == jstar && j0 < i) { best[b][i] = v0; bpS[b][i] = jstar; esc[b][i] = s0; }
        if (j1 == jstar && j1 < i) { best[b][i] = v1; bpS[b][i] = jstar; esc[b][i] = s1; }
        __syncwarp();
    }
    __syncthreads();

    // ---- backtrack ----
    float* bm = out + Bn * Sn * NCn + Bn * Sn * 2;
    for (int idx = tid; idx < Bn * Sn; idx += 64) bm[idx] = 0.f;
    if (tid < Bn) { bpS[tid][0] = 0; esc[tid][0] = 0.f; }
    __syncthreads();
    if (lane == 0) {
        int cur = lengths[b] - 1;
        float acc = 0.f;
        for (int st2 = 0; st2 < Sn; st2++) {
            bm[b * Sn + cur] = 1.0f;
            int prev = bpS[b][cur];
            if (cur > 0) { acc += esc[b][cur]; cur = prev; }
        }
        out[Bn * Sn * NCn + Bn * Sn * 2 + Bn * Sn + b] = acc;
    }
}

// ---------------------------------------------------------------------------
extern "C" void kernel_launch(void* const* d_in, const int* in_sizes, int n_in,
                              void* d_out, int out_size)
{
    const float* x        = (const float*)d_in[0];
    const int*   lengths  = (const int*)  d_in[1];
    const float* w_ih_l0f = (const float*)d_in[2];
    const float* w_hh_l0f = (const float*)d_in[3];
    const float* b_l0f    = (const float*)d_in[4];
    const float* w_ih_l0b = (const float*)d_in[5];
    const float* w_hh_l0b = (const float*)d_in[6];
    const float* b_l0b    = (const float*)d_in[7];
    const float* w_ih_l1f = (const float*)d_in[8];
    const float* w_hh_l1f = (const float*)d_in[9];
    const float* b_l1f    = (const float*)d_in[10];
    const float* w_ih_l1b = (const float*)d_in[11];
    const float* w_hh_l1b = (const float*)d_in[12];
    const float* b_l1b    = (const float*)d_in[13];
    const float* a_s0     = (const float*)d_in[14];
    const float* w_s1     = (const float*)d_in[15];
    const float* b_s1     = (const float*)d_in[16];
    const float* a_s1     = (const float*)d_in[17];
    const float* w_s2     = (const float*)d_in[18];
    const float* b_s2     = (const float*)d_in[19];
    const float* a_c0     = (const float*)d_in[20];
    const float* w_c1     = (const float*)d_in[21];
    const float* b_c1     = (const float*)d_in[22];
    const float* a_c1     = (const float*)d_in[23];
    const float* w_c2     = (const float*)d_in[24];
    const float* b_c2     = (const float*)d_in[25];
    const float* a_b0     = (const float*)d_in[26];
    const float* w_b1     = (const float*)d_in[27];
    const float* b_b1     = (const float*)d_in[28];
    const float* a_b1     = (const float*)d_in[29];
    const float* w_b2     = (const float*)d_in[30];
    const float* b_b2     = (const float*)d_in[31];
    float* out = (float*)d_out;

    // launch order: harness prepends 2 internal kernels; ncu -s 5 -c 1 captures
    // counted launch #6 = program launch #4 = scan_kernel(layer 0).
    prep_wih_kernel<<<(2 * INn * G4 + 2 * F2n * G4 + 255) / 256, 256>>>(
        w_ih_l0f, w_ih_l0b, w_ih_l1f, w_ih_l1b);                                       // 1
    prep_score_kernel<<<(3 * F2n * 128 + 2 * F2n * 80 + 255) / 256, 256>>>(w_s1, w_c1, w_b1); // 2
    pre_kernel<<<dim3(Sn, Bn, 2), G4>>>(x, 0, b_l0f, b_l0b);                           // 3
    scan_kernel<<<dim3(CL, 2, Bn), 256>>>(0, w_hh_l0f, w_hh_l0b);                      // 4 <- profiled
    pre_kernel<<<dim3(Sn, Bn, 2), G4>>>(x, 1, b_l1f, b_l1b);                           // 5
    scan_kernel<<<dim3(CL, 2, Bn), 256>>>(1, w_hh_l1f, w_hh_l1b);                      // 6
    cum_kernel<<<Bn, F2n>>>();                                                         // 7
    feat_kernel<<<dim3(Sn, Bn), 128>>>(a_s0, a_c0, b_c1, a_c1, w_c2, b_c2,
                                       a_b0, b_b1, a_b1, w_b2, b_b2, out);             // 8
    sband_kernel<<<dim3(Sn - 1, Bn), 128>>>(a_s0, b_s1, a_s1, w_s2, b_s2);             // 9
    dp_kernel<<<1, 64>>>(lengths, out);                                                // 10
}